// round 1
// baseline (speedup 1.0000x reference)
#include <cuda_runtime.h>
#include <math.h>

#define NN 8192
#define HH 128
#define NRELC 90
#define NBB 8
#define SII 16

// ---------------- scratch (static device globals; no allocation) ----------------
__device__ float g_x0[NN * HH];
__device__ float g_h[NN * HH];
__device__ float g_agg[NN * HH];
__device__ float g_h2[NN * HH];
__device__ float g_zml[NN * 2 * HH];
__device__ float g_z[NN * HH];
__device__ float g_U[NN * HH];
__device__ float g_h3[NN * HH];
__device__ float g_V[NN * HH];
__device__ float g_S[HH * HH];
__device__ float g_S2[HH * HH];

// ---------------- gather: x0 = embedding[node_ids] ----------------
__global__ void k_gather(const float* __restrict__ emb, const int* __restrict__ ids,
                         float* __restrict__ x0) {
    int i = blockIdx.x * blockDim.x + threadIdx.x;   // float4 index over N*32
    int n = i >> 5, c = i & 31;
    ((float4*)x0)[i] = ((const float4*)(emb + (size_t)ids[n] * HH))[c];
}

// ---------------- zero fill ----------------
__global__ void k_zero(float4* p, int n4) {
    int i = blockIdx.x * blockDim.x + threadIdx.x;
    if (i < n4) p[i] = make_float4(0.f, 0.f, 0.f, 0.f);
}

// ---------------- RGCN edge messages (relation-per-CTA, W in smem) ----------------
// grid = (CHUNKS, NREL); block = 256 (8 warps). Each CTA: load W[rel] (8KB) to smem,
// scan its edge chunk, warp-cooperatively process edges whose etype == rel.
__global__ void k_edges(const float* __restrict__ x, const int* __restrict__ src,
                        const int* __restrict__ dst, const int* __restrict__ et,
                        const float* __restrict__ norm, const float* __restrict__ W,
                        float* __restrict__ agg, int E) {
    __shared__ float sW[NBB * SII * SII];   // 2048 floats
    int rel = blockIdx.y;
    const float4* Wr = (const float4*)(W + rel * 2048);
    for (int i = threadIdx.x; i < 512; i += blockDim.x) ((float4*)sW)[i] = Wr[i];
    __syncthreads();

    int lane = threadIdx.x & 31;
    int warp = threadIdx.x >> 5;
    int nwarp = blockDim.x >> 5;
    int per_chunk = (E + gridDim.x - 1) / gridDim.x;
    int e0 = blockIdx.x * per_chunk;
    int e1 = min(E, e0 + per_chunk);

    int b  = lane >> 2;            // block index (0..7) this lane outputs into
    int o0 = (lane & 3) * 4;       // first of 4 output cols within block

    for (int base = e0 + warp * 32; base < e1; base += nwarp * 32) {
        int e = base + lane;
        int myet = (e < e1) ? et[e] : -1;
        unsigned m = __ballot_sync(0xffffffffu, myet == rel);
        while (m) {
            int bit = __ffs(m) - 1;
            m &= m - 1;
            int ee = base + bit;
            int s  = src[ee];                // broadcast load (same addr all lanes)
            int d  = dst[ee];
            float nr = norm[ee];
            float4 xv = ((const float4*)(x + (size_t)s * HH))[lane];  // lane owns x[4l..4l+3]
            float4 a = make_float4(0.f, 0.f, 0.f, 0.f);
            #pragma unroll
            for (int c = 0; c < 4; c++) {
                int sl = b * 4 + c;          // lane holding x[b*16 + c*4 .. +3]
                float4 xi;
                xi.x = __shfl_sync(0xffffffffu, xv.x, sl);
                xi.y = __shfl_sync(0xffffffffu, xv.y, sl);
                xi.z = __shfl_sync(0xffffffffu, xv.z, sl);
                xi.w = __shfl_sync(0xffffffffu, xv.w, sl);
                int ib = b * 256 + (c * 4) * 16 + o0;
                float4 w0 = *(const float4*)&sW[ib];
                float4 w1 = *(const float4*)&sW[ib + 16];
                float4 w2 = *(const float4*)&sW[ib + 32];
                float4 w3 = *(const float4*)&sW[ib + 48];
                a.x += xi.x * w0.x + xi.y * w1.x + xi.z * w2.x + xi.w * w3.x;
                a.y += xi.x * w0.y + xi.y * w1.y + xi.z * w2.y + xi.w * w3.y;
                a.z += xi.x * w0.z + xi.y * w1.z + xi.z * w2.z + xi.w * w3.z;
                a.w += xi.x * w0.w + xi.y * w1.w + xi.z * w2.w + xi.w * w3.w;
            }
            float* ap = agg + (size_t)d * HH + lane * 4;
            atomicAdd(ap + 0, a.x * nr);
            atomicAdd(ap + 1, a.y * nr);
            atomicAdd(ap + 2, a.z * nr);
            atomicAdd(ap + 3, a.w * nr);
        }
    }
}

// ---------------- GEMM: C[N,Hout] = A[N,128] @ B[128,Hout] + bias (+add1) (+relu) ----
// blockDim.x = Hout (thread = output col), 32 rows per block, A tile in smem.
__global__ void k_gemm(const float* __restrict__ A, const float* __restrict__ B,
                       const float* __restrict__ add1, const float* __restrict__ bias,
                       float* __restrict__ C, int Hout, int relu) {
    __shared__ float sA[32][HH];
    int t = threadIdx.x;
    int row0 = blockIdx.x * 32;
    const float4* Af = (const float4*)(A + (size_t)row0 * HH);
    float4* sAf = (float4*)&sA[0][0];
    for (int idx = t; idx < 32 * HH / 4; idx += blockDim.x) sAf[idx] = Af[idx];
    __syncthreads();

    float acc[32];
    #pragma unroll
    for (int r = 0; r < 32; r++) acc[r] = 0.f;

    #pragma unroll 4
    for (int k = 0; k < HH; k++) {
        float bk = B[k * Hout + t];
        #pragma unroll
        for (int r = 0; r < 32; r++) acc[r] += sA[r][k] * bk;
    }

    float bv = bias ? bias[t] : 0.f;
    #pragma unroll
    for (int r = 0; r < 32; r++) {
        size_t idx = (size_t)(row0 + r) * Hout + t;
        float v = acc[r] + bv;
        if (add1) v += add1[idx];
        if (relu) v = fmaxf(v, 0.f);
        C[idx] = v;
    }
}

// ---------------- S[128,128] += A^T @ B over a 64-row chunk (atomic accumulate) ----
// grid.x = N/64 chunks; block 256: t = j + 128*ig; thread accumulates 64 i's.
__global__ void k_atb(const float* __restrict__ A, const float* __restrict__ Bm,
                      float* __restrict__ S) {
    __shared__ float sA[8][HH];
    __shared__ float sB[8][HH];
    int t = threadIdx.x;
    int j = t & 127, ig = t >> 7;
    float acc[64];
    #pragma unroll
    for (int i = 0; i < 64; i++) acc[i] = 0.f;
    int n0 = blockIdx.x * 64;
    for (int tile = 0; tile < 8; tile++) {
        int nb = n0 + tile * 8;
        ((float4*)sA)[t] = ((const float4*)(A + (size_t)nb * HH))[t];
        ((float4*)sB)[t] = ((const float4*)(Bm + (size_t)nb * HH))[t];
        __syncthreads();
        #pragma unroll
        for (int nn = 0; nn < 8; nn++) {
            float bv = sB[nn][j];
            #pragma unroll
            for (int ii = 0; ii < 64; ii++) acc[ii] += sA[nn][ig * 64 + ii] * bv;
        }
        __syncthreads();
    }
    #pragma unroll
    for (int ii = 0; ii < 64; ii++)
        atomicAdd(&S[(ig * 64 + ii) * HH + j], acc[ii]);
}

// ---------------- z = mean + exp(log_std) * eps ----------------
__global__ void k_zcomb(const float* __restrict__ zml, const float* __restrict__ eps,
                        float* __restrict__ z) {
    int i = blockIdx.x * blockDim.x + threadIdx.x;   // over N*H
    int n = i >> 7, c = i & 127;
    z[i] = zml[n * 256 + c] + expf(zml[n * 256 + 128 + c]) * eps[i];
}

// ---------------- host ----------------
extern "C" void kernel_launch(void* const* d_in, const int* in_sizes, int n_in,
                              void* d_out, int out_size) {
    const int*   node_ids = (const int*)d_in[0];
    const int*   src   = (const int*)d_in[1];
    const int*   dst   = (const int*)d_in[2];
    const int*   et    = (const int*)d_in[3];
    const float* norm  = (const float*)d_in[4];
    const float* eps   = (const float*)d_in[5];
    const float* emb   = (const float*)d_in[6];
    const float* W0    = (const float*)d_in[7];
    const float* loop0 = (const float*)d_in[8];
    const float* b0    = (const float*)d_in[9];
    const float* W1    = (const float*)d_in[10];
    const float* loop1 = (const float*)d_in[11];
    const float* b1    = (const float*)d_in[12];
    const float* Wz    = (const float*)d_in[13];
    const float* bz    = (const float*)d_in[14];
    const float* Wi    = (const float*)d_in[15];
    const float* bi    = (const float*)d_in[16];
    const float* hbi   = (const float*)d_in[17];
    const float* Wo    = (const float*)d_in[18];
    const float* bo    = (const float*)d_in[19];
    const float* hbo   = (const float*)d_in[20];
    int E = in_sizes[1];

    float *x0, *h, *agg, *h2, *zml, *z, *U, *h3, *V, *S, *S2;
    cudaGetSymbolAddress((void**)&x0,  g_x0);
    cudaGetSymbolAddress((void**)&h,   g_h);
    cudaGetSymbolAddress((void**)&agg, g_agg);
    cudaGetSymbolAddress((void**)&h2,  g_h2);
    cudaGetSymbolAddress((void**)&zml, g_zml);
    cudaGetSymbolAddress((void**)&z,   g_z);
    cudaGetSymbolAddress((void**)&U,   g_U);
    cudaGetSymbolAddress((void**)&h3,  g_h3);
    cudaGetSymbolAddress((void**)&V,   g_V);
    cudaGetSymbolAddress((void**)&S,   g_S);
    cudaGetSymbolAddress((void**)&S2,  g_S2);

    float* out = (float*)d_out;

    const int NH4 = NN * HH / 4;         // 262144 float4
    dim3 egrid(16, NRELC);

    // x0 = embedding[node_ids]
    k_gather<<<NN * 32 / 256, 256>>>(emb, node_ids, x0);

    // RGCN layer 0 (relu)
    k_zero<<<(NH4 + 255) / 256, 256>>>((float4*)agg, NH4);
    k_edges<<<egrid, 256>>>(x0, src, dst, et, norm, W0, agg, E);
    k_gemm<<<NN / 32, 128>>>(x0, loop0, agg, b0, h, 128, 1);

    // RGCN layer 1 (no act)
    k_zero<<<(NH4 + 255) / 256, 256>>>((float4*)agg, NH4);
    k_edges<<<egrid, 256>>>(h, src, dst, et, norm, W1, agg, E);
    k_gemm<<<NN / 32, 128>>>(h, loop1, agg, b1, h2, 128, 0);

    // VAE head
    k_gemm<<<NN / 32, 256>>>(h2, Wz, nullptr, bz, zml, 256, 0);
    k_zcomb<<<NN * HH / 256, 256>>>(zml, eps, z);

    // decode 1: h3 = z @ (z^T @ (z@Wi + bi + x0)) + hbi
    k_gemm<<<NN / 32, 128>>>(z, Wi, x0, bi, U, 128, 0);
    k_zero<<<(HH * HH / 4 + 255) / 256, 256>>>((float4*)S, HH * HH / 4);
    k_atb<<<NN / 64, 256>>>(z, U, S);
    k_gemm<<<NN / 32, 128>>>(z, S, nullptr, hbi, h3, 128, 0);

    // decode 2: out = h3 @ (h3^T @ (h3@Wo + bo + x0)) + hbo
    k_gemm<<<NN / 32, 128>>>(h3, Wo, x0, bo, V, 128, 0);
    k_zero<<<(HH * HH / 4 + 255) / 256, 256>>>((float4*)S2, HH * HH / 4);
    k_atb<<<NN / 64, 256>>>(h3, V, S2);
    k_gemm<<<NN / 32, 128>>>(h3, S2, nullptr, hbo, out, 128, 0);
}

// round 2
// speedup vs baseline: 1.1727x; 1.1727x over previous
#include <cuda_runtime.h>
#include <math.h>

#define NN 8192
#define HH 128
#define NRELC 90
#define NBB 8
#define SII 16

// ---------------- scratch (static device globals; no allocation) ----------------
__device__ float g_x0[NN * HH];
__device__ float g_h[NN * HH];
__device__ float g_h2[NN * HH];
__device__ float g_zml[NN * 2 * HH];
__device__ float g_z[NN * HH];
__device__ float g_U[NN * HH];
__device__ float g_h3[NN * HH];
__device__ float g_V[NN * HH];
__device__ float g_S[HH * HH];
__device__ float g_S2[HH * HH];

// vectorized fp32 atomic add (sm_90+)
__device__ __forceinline__ void red4(float* p, float a, float b, float c, float d) {
    asm volatile("red.global.add.v4.f32 [%0], {%1,%2,%3,%4};"
                 :: "l"(p), "f"(a), "f"(b), "f"(c), "f"(d) : "memory");
}

// ---------------- gather: x0 = embedding[node_ids] ----------------
__global__ void k_gather(const float* __restrict__ emb, const int* __restrict__ ids,
                         float* __restrict__ x0) {
    int i = blockIdx.x * blockDim.x + threadIdx.x;   // float4 index over N*32
    int n = i >> 5, c = i & 31;
    ((float4*)x0)[i] = ((const float4*)(emb + (size_t)ids[n] * HH))[c];
}

// ---------------- zero fill ----------------
__global__ void k_zero(float4* p, int n4) {
    int i = blockIdx.x * blockDim.x + threadIdx.x;
    if (i < n4) p[i] = make_float4(0.f, 0.f, 0.f, 0.f);
}

// ---------------- relu in place ----------------
__global__ void k_relu(float4* p) {
    int i = blockIdx.x * blockDim.x + threadIdx.x;
    float4 v = p[i];
    v.x = fmaxf(v.x, 0.f); v.y = fmaxf(v.y, 0.f);
    v.z = fmaxf(v.z, 0.f); v.w = fmaxf(v.w, 0.f);
    p[i] = v;
}

// ---------------- RGCN edge messages (relation-per-CTA, W in smem) ----------------
// Accumulates directly into `acc` (pre-filled with self-loop gemm + bias) via red.v4.
__global__ void k_edges(const float* __restrict__ x, const int* __restrict__ src,
                        const int* __restrict__ dst, const int* __restrict__ et,
                        const float* __restrict__ norm, const float* __restrict__ W,
                        float* __restrict__ acc_out, int E) {
    __shared__ float sW[NBB * SII * SII];   // 2048 floats = 8KB
    int rel = blockIdx.y;
    const float4* Wr = (const float4*)(W + rel * 2048);
    for (int i = threadIdx.x; i < 512; i += blockDim.x) ((float4*)sW)[i] = Wr[i];
    __syncthreads();

    int lane = threadIdx.x & 31;
    int warp = threadIdx.x >> 5;
    int nwarp = blockDim.x >> 5;
    int per_chunk = (E + gridDim.x - 1) / gridDim.x;
    int e0 = blockIdx.x * per_chunk;
    int e1 = min(E, e0 + per_chunk);

    int b  = lane >> 2;            // block index (0..7) this lane outputs into
    int o0 = (lane & 3) * 4;       // first of 4 output cols within block

    for (int base = e0 + warp * 32; base < e1; base += nwarp * 32) {
        int e = base + lane;
        int myet = (e < e1) ? et[e] : -1;
        unsigned m = __ballot_sync(0xffffffffu, myet == rel);
        while (m) {
            int bit = __ffs(m) - 1;
            m &= m - 1;
            int ee = base + bit;
            int s  = src[ee];
            int d  = dst[ee];
            float nr = norm[ee];
            float4 xv = ((const float4*)(x + (size_t)s * HH))[lane];
            float4 a = make_float4(0.f, 0.f, 0.f, 0.f);
            #pragma unroll
            for (int c = 0; c < 4; c++) {
                int sl = b * 4 + c;          // lane holding x[b*16 + c*4 .. +3]
                float4 xi;
                xi.x = __shfl_sync(0xffffffffu, xv.x, sl);
                xi.y = __shfl_sync(0xffffffffu, xv.y, sl);
                xi.z = __shfl_sync(0xffffffffu, xv.z, sl);
                xi.w = __shfl_sync(0xffffffffu, xv.w, sl);
                int ib = b * 256 + (c * 4) * 16 + o0;
                float4 w0 = *(const float4*)&sW[ib];
                float4 w1 = *(const float4*)&sW[ib + 16];
                float4 w2 = *(const float4*)&sW[ib + 32];
                float4 w3 = *(const float4*)&sW[ib + 48];
                a.x += xi.x * w0.x + xi.y * w1.x + xi.z * w2.x + xi.w * w3.x;
                a.y += xi.x * w0.y + xi.y * w1.y + xi.z * w2.y + xi.w * w3.y;
                a.z += xi.x * w0.z + xi.y * w1.z + xi.z * w2.z + xi.w * w3.z;
                a.w += xi.x * w0.w + xi.y * w1.w + xi.z * w2.w + xi.w * w3.w;
            }
            red4(acc_out + (size_t)d * HH + lane * 4, a.x * nr, a.y * nr, a.z * nr, a.w * nr);
        }
    }
}

// ---------------- register-tiled GEMM: C[N,Hout] = A[N,128] @ B[128,Hout] ----------
// CTA tile 64 rows x 128 cols; 256 threads; thread tile 4x8. grid=(N/64, Hout/128).
__global__ void k_gemm2(const float* __restrict__ A, const float* __restrict__ B,
                        const float* __restrict__ add1, const float* __restrict__ bias,
                        float* __restrict__ C, int Hout, int relu) {
    __shared__ float sA[64][33];
    __shared__ float sB[32][128];
    int t = threadIdx.x;
    int tx = t & 15, ty = t >> 4;
    int row0 = blockIdx.x * 64;
    int col0 = blockIdx.y * 128;
    int r0 = ty * 4;
    int c0 = tx * 8;

    float acc[4][8];
    #pragma unroll
    for (int i = 0; i < 4; i++)
        #pragma unroll
        for (int j = 0; j < 8; j++) acc[i][j] = 0.f;

    for (int k0 = 0; k0 < HH; k0 += 32) {
        // stage A tile 64x32
        #pragma unroll
        for (int p = 0; p < 2; p++) {
            int idx = t + p * 256;
            int r = idx >> 3, f4 = idx & 7;
            float4 v = *(const float4*)&A[(size_t)(row0 + r) * HH + k0 + f4 * 4];
            sA[r][f4 * 4 + 0] = v.x;
            sA[r][f4 * 4 + 1] = v.y;
            sA[r][f4 * 4 + 2] = v.z;
            sA[r][f4 * 4 + 3] = v.w;
        }
        // stage B tile 32x128
        #pragma unroll
        for (int p = 0; p < 4; p++) {
            int idx = t + p * 256;
            int kk = idx >> 5, f4 = idx & 31;
            *(float4*)&sB[kk][f4 * 4] =
                *(const float4*)&B[(size_t)(k0 + kk) * Hout + col0 + f4 * 4];
        }
        __syncthreads();

        #pragma unroll 8
        for (int kk = 0; kk < 32; kk++) {
            float a0 = sA[r0 + 0][kk];
            float a1 = sA[r0 + 1][kk];
            float a2 = sA[r0 + 2][kk];
            float a3 = sA[r0 + 3][kk];
            float4 b0 = *(float4*)&sB[kk][c0];
            float4 b1 = *(float4*)&sB[kk][c0 + 4];
            acc[0][0] += a0 * b0.x; acc[0][1] += a0 * b0.y; acc[0][2] += a0 * b0.z; acc[0][3] += a0 * b0.w;
            acc[0][4] += a0 * b1.x; acc[0][5] += a0 * b1.y; acc[0][6] += a0 * b1.z; acc[0][7] += a0 * b1.w;
            acc[1][0] += a1 * b0.x; acc[1][1] += a1 * b0.y; acc[1][2] += a1 * b0.z; acc[1][3] += a1 * b0.w;
            acc[1][4] += a1 * b1.x; acc[1][5] += a1 * b1.y; acc[1][6] += a1 * b1.z; acc[1][7] += a1 * b1.w;
            acc[2][0] += a2 * b0.x; acc[2][1] += a2 * b0.y; acc[2][2] += a2 * b0.z; acc[2][3] += a2 * b0.w;
            acc[2][4] += a2 * b1.x; acc[2][5] += a2 * b1.y; acc[2][6] += a2 * b1.z; acc[2][7] += a2 * b1.w;
            acc[3][0] += a3 * b0.x; acc[3][1] += a3 * b0.y; acc[3][2] += a3 * b0.z; acc[3][3] += a3 * b0.w;
            acc[3][4] += a3 * b1.x; acc[3][5] += a3 * b1.y; acc[3][6] += a3 * b1.z; acc[3][7] += a3 * b1.w;
        }
        __syncthreads();
    }

    float bv[8];
    #pragma unroll
    for (int j = 0; j < 8; j++) bv[j] = bias ? bias[col0 + c0 + j] : 0.f;

    #pragma unroll
    for (int i = 0; i < 4; i++) {
        size_t base = (size_t)(row0 + r0 + i) * Hout + col0 + c0;
        float v[8];
        #pragma unroll
        for (int j = 0; j < 8; j++) {
            v[j] = acc[i][j] + bv[j];
            if (add1) v[j] += add1[base + j];
            if (relu) v[j] = fmaxf(v[j], 0.f);
        }
        *(float4*)&C[base]     = make_float4(v[0], v[1], v[2], v[3]);
        *(float4*)&C[base + 4] = make_float4(v[4], v[5], v[6], v[7]);
    }
}

// ---------------- S[128,128] += A^T @ B over 64-row chunk (8x8 tiles, red.v4) ------
__global__ void k_atb2(const float* __restrict__ A, const float* __restrict__ Bm,
                       float* __restrict__ S) {
    __shared__ float sA[16][128];
    __shared__ float sB[16][128];
    int t = threadIdx.x;
    int jx = t & 15, iy = t >> 4;
    float acc[8][8];
    #pragma unroll
    for (int i = 0; i < 8; i++)
        #pragma unroll
        for (int j = 0; j < 8; j++) acc[i][j] = 0.f;

    int n0 = blockIdx.x * 64;
    for (int st = 0; st < 4; st++) {
        int nb = n0 + st * 16;
        #pragma unroll
        for (int p = 0; p < 2; p++) {
            int idx = t + p * 256;
            int r = idx >> 5, f4 = idx & 31;
            *(float4*)&sA[r][f4 * 4] = *(const float4*)&A[(size_t)(nb + r) * HH + f4 * 4];
            *(float4*)&sB[r][f4 * 4] = *(const float4*)&Bm[(size_t)(nb + r) * HH + f4 * 4];
        }
        __syncthreads();
        #pragma unroll 4
        for (int n = 0; n < 16; n++) {
            float4 a0 = *(float4*)&sA[n][iy * 8];
            float4 a1 = *(float4*)&sA[n][iy * 8 + 4];
            float4 b0 = *(float4*)&sB[n][jx * 8];
            float4 b1 = *(float4*)&sB[n][jx * 8 + 4];
            float av[8] = {a0.x, a0.y, a0.z, a0.w, a1.x, a1.y, a1.z, a1.w};
            float bw[8] = {b0.x, b0.y, b0.z, b0.w, b1.x, b1.y, b1.z, b1.w};
            #pragma unroll
            for (int i = 0; i < 8; i++)
                #pragma unroll
                for (int j = 0; j < 8; j++) acc[i][j] += av[i] * bw[j];
        }
        __syncthreads();
    }

    #pragma unroll
    for (int i = 0; i < 8; i++) {
        float* p = S + (size_t)(iy * 8 + i) * HH + jx * 8;
        red4(p,     acc[i][0], acc[i][1], acc[i][2], acc[i][3]);
        red4(p + 4, acc[i][4], acc[i][5], acc[i][6], acc[i][7]);
    }
}

// ---------------- z = mean + exp(log_std) * eps ----------------
__global__ void k_zcomb(const float* __restrict__ zml, const float* __restrict__ eps,
                        float* __restrict__ z) {
    int i = blockIdx.x * blockDim.x + threadIdx.x;   // over N*H
    int n = i >> 7, c = i & 127;
    z[i] = zml[n * 256 + c] + expf(zml[n * 256 + 128 + c]) * eps[i];
}

// ---------------- host ----------------
extern "C" void kernel_launch(void* const* d_in, const int* in_sizes, int n_in,
                              void* d_out, int out_size) {
    const int*   node_ids = (const int*)d_in[0];
    const int*   src   = (const int*)d_in[1];
    const int*   dst   = (const int*)d_in[2];
    const int*   et    = (const int*)d_in[3];
    const float* norm  = (const float*)d_in[4];
    const float* eps   = (const float*)d_in[5];
    const float* emb   = (const float*)d_in[6];
    const float* W0    = (const float*)d_in[7];
    const float* loop0 = (const float*)d_in[8];
    const float* b0    = (const float*)d_in[9];
    const float* W1    = (const float*)d_in[10];
    const float* loop1 = (const float*)d_in[11];
    const float* b1    = (const float*)d_in[12];
    const float* Wz    = (const float*)d_in[13];
    const float* bz    = (const float*)d_in[14];
    const float* Wi    = (const float*)d_in[15];
    const float* bi    = (const float*)d_in[16];
    const float* hbi   = (const float*)d_in[17];
    const float* Wo    = (const float*)d_in[18];
    const float* bo    = (const float*)d_in[19];
    const float* hbo   = (const float*)d_in[20];
    int E = in_sizes[1];

    float *x0, *h, *h2, *zml, *z, *U, *h3, *V, *S, *S2;
    cudaGetSymbolAddress((void**)&x0,  g_x0);
    cudaGetSymbolAddress((void**)&h,   g_h);
    cudaGetSymbolAddress((void**)&h2,  g_h2);
    cudaGetSymbolAddress((void**)&zml, g_zml);
    cudaGetSymbolAddress((void**)&z,   g_z);
    cudaGetSymbolAddress((void**)&U,   g_U);
    cudaGetSymbolAddress((void**)&h3,  g_h3);
    cudaGetSymbolAddress((void**)&V,   g_V);
    cudaGetSymbolAddress((void**)&S,   g_S);
    cudaGetSymbolAddress((void**)&S2,  g_S2);

    float* out = (float*)d_out;

    const int NH4 = NN * HH / 4;
    dim3 egrid(32, NRELC);
    dim3 g1(NN / 64, 1), g2(NN / 64, 2);

    // x0 = embedding[node_ids]
    k_gather<<<NN * 32 / 256, 256>>>(emb, node_ids, x0);

    // RGCN layer 0: h = relu(x0@loop0 + b0 + sum_edges)
    k_gemm2<<<g1, 256>>>(x0, loop0, nullptr, b0, h, 128, 0);
    k_edges<<<egrid, 256>>>(x0, src, dst, et, norm, W0, h, E);
    k_relu<<<NH4 / 256, 256>>>((float4*)h);

    // RGCN layer 1 (no act): h2 = h@loop1 + b1 + sum_edges
    k_gemm2<<<g1, 256>>>(h, loop1, nullptr, b1, h2, 128, 0);
    k_edges<<<egrid, 256>>>(h, src, dst, et, norm, W1, h2, E);

    // VAE head
    k_gemm2<<<g2, 256>>>(h2, Wz, nullptr, bz, zml, 256, 0);
    k_zcomb<<<NN * HH / 256, 256>>>(zml, eps, z);

    // decode 1: h3 = z @ (z^T @ (z@Wi + bi + x0)) + hbi
    k_gemm2<<<g1, 256>>>(z, Wi, x0, bi, U, 128, 0);
    k_zero<<<(HH * HH / 4 + 255) / 256, 256>>>((float4*)S, HH * HH / 4);
    k_atb2<<<NN / 64, 256>>>(z, U, S);
    k_gemm2<<<g1, 256>>>(z, S, nullptr, hbi, h3, 128, 0);

    // decode 2: out = h3 @ (h3^T @ (h3@Wo + bo + x0)) + hbo
    k_gemm2<<<g1, 256>>>(h3, Wo, x0, bo, V, 128, 0);
    k_zero<<<(HH * HH / 4 + 255) / 256, 256>>>((float4*)S2, HH * HH / 4);
    k_atb2<<<NN / 64, 256>>>(h3, V, S2);
    k_gemm2<<<g1, 256>>>(h3, S2, nullptr, hbo, out, 128, 0);
}